// round 1
// baseline (speedup 1.0000x reference)
#include <cuda_runtime.h>

#define NB 16
#define NP 65536
#define NT 64
#define APT 8
#define THR 256
#define CHUNK (APT*THR)   /* 2048 anchors per block */
#define NWARP (THR/32)

__device__ unsigned long long g_bp[NB*NT];     // packed (u_bits<<32)|~anchor_idx per (b,t)
__device__ unsigned char g_match[NB*NP];       // bit7 = pos, bits0-6 = best truth idx
__device__ double g_acc[3];                    // 0: smoothL1 sum, 1: pos count, 2: CE sum

__global__ void k_init(){
    int i = threadIdx.x;
    if (i < NB*NT) g_bp[i] = 0xFFFFFFFFull;    // u = 0, idx = 0 (first-index default)
    if (i < 3)     g_acc[i] = 0.0;
}

// compare iou via cross-multiplication: candidate (ci,cs,cx) beats (bi,bs,bx)
// iff ci/cs > bi/bs, ties broken by lower anchor index (jnp.argmax = first max).
__device__ __forceinline__ void fold(float &bi, float &bs, unsigned &bx,
                                     float ci, float cs, unsigned cx){
    float p1 = bi * cs;
    float p2 = ci * bs;
    if (p2 > p1 || (p2 == p1 && cx < bx)){ bi = ci; bs = cs; bx = cx; }
}

__global__ __launch_bounds__(THR)
void k_match(const float4* __restrict__ anchors, const float4* __restrict__ targets){
    const int b    = blockIdx.y;
    const int base = blockIdx.x * CHUNK;
    const int tid  = threadIdx.x;
    const int lane = tid & 31, wid = tid >> 5;

    __shared__ float4   s_tr[NT];
    __shared__ float    s_ta[NT];
    __shared__ float    s_ri[NT][NWARP];
    __shared__ float    s_rs[NT][NWARP];
    __shared__ unsigned s_rx[NT][NWARP];

    if (tid < NT){
        float4 t4 = targets[b*NT + tid];
        s_tr[tid] = t4;
        s_ta[tid] = (t4.z - t4.x) * (t4.w - t4.y);
    }
    __syncthreads();

    float4 A[APT]; float aa[APT];
    float bi[APT], bs[APT]; int bt[APT];
#pragma unroll
    for (int k = 0; k < APT; k++){
        A[k]  = anchors[b*NP + base + k*THR + tid];
        aa[k] = (A[k].z - A[k].x) * (A[k].w - A[k].y);
        bi[k] = -1.0f; bs[k] = 1.0f; bt[k] = 0;   // sentinel: t=0 always wins first
    }

    for (int t = 0; t < NT; t++){
        const float4 tr = s_tr[t];
        const float  at = s_ta[t];
        float li = 0.0f, ls = 0.0f; unsigned lx = 0xFFFFFFFFu;
#pragma unroll
        for (int k = 0; k < APT; k++){
            float ltx = fmaxf(tr.x, A[k].x);
            float lty = fmaxf(tr.y, A[k].y);
            float rbx = fminf(tr.z, A[k].z);
            float rby = fminf(tr.w, A[k].w);
            float w   = fmaxf(rbx - ltx, 0.0f);
            float h   = fmaxf(rby - lty, 0.0f);
            float inter = w * h;
            float S     = at + aa[k];
            // anchor side: strictly-greater keeps earliest t (argmax axis=0 = first)
            float p1 = bi[k]*S, p2 = inter*bs[k];
            if (p2 > p1){ bi[k] = inter; bs[k] = S; bt[k] = t; }
            // prior side: best anchor (lowest index on tie) for this truth
            fold(li, ls, lx, inter, S, (unsigned)(base + k*THR + tid));
        }
        // warp-level reduce for the prior side
#pragma unroll
        for (int off = 16; off > 0; off >>= 1){
            float ci    = __shfl_down_sync(0xFFFFFFFFu, li, off);
            float cs    = __shfl_down_sync(0xFFFFFFFFu, ls, off);
            unsigned cx = __shfl_down_sync(0xFFFFFFFFu, lx, off);
            fold(li, ls, lx, ci, cs, cx);
        }
        if (lane == 0){ s_ri[t][wid] = li; s_rs[t][wid] = ls; s_rx[t][wid] = lx; }
    }

    // per-anchor result byte: pos (iou >= 0.5 <=> 3*inter >= S) + best truth idx
#pragma unroll
    for (int k = 0; k < APT; k++){
        bool pos = (3.0f * bi[k] >= bs[k]);
        g_match[b*NP + base + k*THR + tid] = (unsigned char)((pos ? 0x80u : 0u) | (unsigned)bt[k]);
    }

    __syncthreads();
    // cross-warp reduce + one division per (block, truth), then global atomicMax
    if (tid < NT){
        float li = s_ri[tid][0], ls = s_rs[tid][0]; unsigned lx = s_rx[tid][0];
#pragma unroll
        for (int w = 1; w < NWARP; w++)
            fold(li, ls, lx, s_ri[tid][w], s_rs[tid][w], s_rx[tid][w]);
        if (li > 0.0f){
            float u = __fdividef(li, ls);   // monotone with iou = inter/(S-inter)
            unsigned long long key =
                ((unsigned long long)__float_as_uint(u) << 32) | (unsigned long long)(~lx);
            atomicMax(&g_bp[b*NT + tid], key);
        }
    }
}

// force-match: per batch, sequentially (last t wins on duplicates, like the torch loop)
__global__ void k_force(){
    int b = threadIdx.x;
    if (b < NB){
#pragma unroll 1
        for (int t = 0; t < NT; t++){
            unsigned idx = ~((unsigned)(g_bp[b*NT + t] & 0xFFFFFFFFull));
            g_match[b*NP + idx] = (unsigned char)(0x80u | (unsigned)t);
        }
    }
}

__global__ __launch_bounds__(THR)
void k_loss(const float4* __restrict__ loc, const float4* __restrict__ conf4,
            const float4* __restrict__ anchors, const float4* __restrict__ targets){
    const int b    = blockIdx.y;
    const int tid  = threadIdx.x;
    const int base = blockIdx.x * (THR*4) + tid*4;   // 4 consecutive anchors per thread

    __shared__ float4 s_tr[NT];
    if (tid < NT) s_tr[tid] = targets[b*NT + tid];
    __syncthreads();

    unsigned mu = *(const unsigned*)&g_match[b*NP + base];
    float4 c01 = conf4[(b*NP + base)/2 + 0];
    float4 c23 = conf4[(b*NP + base)/2 + 1];

    float sl = 0.0f, ce = 0.0f, cnt = 0.0f;
#pragma unroll
    for (int i = 0; i < 4; i++){
        unsigned m = (mu >> (8*i)) & 0xFFu;
        float x0, x1;
        if (i == 0){ x0 = c01.x; x1 = c01.y; }
        else if (i == 1){ x0 = c01.z; x1 = c01.w; }
        else if (i == 2){ x0 = c23.x; x1 = c23.y; }
        else { x0 = c23.z; x1 = c23.w; }
        // ce = logsumexp(x0,x1) - x_label
        float mx  = fmaxf(x0, x1), mn = fminf(x0, x1);
        float lse = mx + __logf(1.0f + __expf(mn - mx));
        float xl  = (m & 0x80u) ? x1 : x0;
        ce += lse - xl;

        if (m & 0x80u){   // positive: encode + smooth-L1
            int p = base + i;
            float4 a  = anchors[b*NP + p];
            float4 l  = loc[b*NP + p];
            float4 tr = s_tr[m & 0x7Fu];
            float aw  = a.z - a.x,  ah  = a.w - a.y;
            float acx = (a.x + a.z)*0.5f, acy = (a.y + a.w)*0.5f;
            float mw  = tr.z - tr.x, mh = tr.w - tr.y;
            float mcx = (tr.x + tr.z)*0.5f, mcy = (tr.y + tr.w)*0.5f;
            float rw  = __fdividef(1.0f, aw), rh = __fdividef(1.0f, ah);
            float g0 = (mcx - acx) * rw * 10.0f;     // /(0.1*aw)
            float g1 = (mcy - acy) * rh * 10.0f;
            float g2 = __logf(mw * rw) * 5.0f;       // /0.2
            float g3 = __logf(mh * rh) * 5.0f;
            float d0 = fabsf(l.x - g0), d1 = fabsf(l.y - g1);
            float d2 = fabsf(l.z - g2), d3 = fabsf(l.w - g3);
            sl += (d0 < 1.0f ? 0.5f*d0*d0 : d0 - 0.5f);
            sl += (d1 < 1.0f ? 0.5f*d1*d1 : d1 - 0.5f);
            sl += (d2 < 1.0f ? 0.5f*d2*d2 : d2 - 0.5f);
            sl += (d3 < 1.0f ? 0.5f*d3*d3 : d3 - 0.5f);
            cnt += 1.0f;
        }
    }

#pragma unroll
    for (int off = 16; off > 0; off >>= 1){
        sl  += __shfl_down_sync(0xFFFFFFFFu, sl,  off);
        ce  += __shfl_down_sync(0xFFFFFFFFu, ce,  off);
        cnt += __shfl_down_sync(0xFFFFFFFFu, cnt, off);
    }
    __shared__ float r0[NWARP], r1[NWARP], r2[NWARP];
    int lane = tid & 31, wid = tid >> 5;
    if (lane == 0){ r0[wid] = sl; r1[wid] = ce; r2[wid] = cnt; }
    __syncthreads();
    if (tid == 0){
        float a = 0.f, c = 0.f, n = 0.f;
#pragma unroll
        for (int w = 0; w < NWARP; w++){ a += r0[w]; c += r1[w]; n += r2[w]; }
        atomicAdd(&g_acc[0], (double)a);
        atomicAdd(&g_acc[1], (double)n);
        atomicAdd(&g_acc[2], (double)c);
    }
}

__global__ void k_fin(float* out){
    // loss_l / cnt_l + sum(ce) / (P * B * P)
    double loss = g_acc[0] / g_acc[1]
                + g_acc[2] / ((double)NP * (double)NB * (double)NP);
    out[0] = (float)loss;
}

extern "C" void kernel_launch(void* const* d_in, const int* in_sizes, int n_in,
                              void* d_out, int out_size){
    const float4* loc     = (const float4*)d_in[0];
    const float4* conf4   = (const float4*)d_in[1];
    const float4* anchors = (const float4*)d_in[2];
    const float4* targets = (const float4*)d_in[3];
    float* out = (float*)d_out;

    k_init<<<1, 1024>>>();
    k_match<<<dim3(NP/CHUNK, NB), THR>>>(anchors, targets);
    k_force<<<1, 32>>>();
    k_loss<<<dim3(NP/(THR*4), NB), THR>>>(loc, conf4, anchors, targets);
    k_fin<<<1, 1>>>(out);
}